// round 1
// baseline (speedup 1.0000x reference)
#include <cuda_runtime.h>
#include <cuda_bf16.h>

// ---------------- problem constants ----------------
#define NN 165888            // B*81 nodes
#define BB 2048
#define EP 1620
#define ET (BB*EP)           // 3,317,760 edges (plus NN implicit self loops)

// ---------------- device scratch (no allocation allowed) ----------------
__device__ int   g_deg[NN];
__device__ int   g_fill[NN];
__device__ int   g_start[NN];
__device__ float g_dinv[NN];
__device__ float g_selfw[NN];
__device__ int2  g_entries[ET];      // (src, norm-as-bits)
__device__ float g_bufA[NN * 64];
__device__ float g_bufB[NN * 64];
__device__ int   g_counter;

// ---------------- graph build ----------------
__global__ void zero_kernel() {
    int i = blockIdx.x * 256 + threadIdx.x;
    if (i < NN) { g_deg[i] = 0; g_fill[i] = 0; }
    if (i == 0) g_counter = 0;
}

__global__ void count_kernel(const int* __restrict__ ei) {
    int t = blockIdx.x * 256 + threadIdx.x;
    if (t >= ET) return;
    int b = t / EP, j = t - b * EP;
    int dst = ei[(b * 2 + 1) * EP + j];
    atomicAdd(&g_deg[dst], 1);
}

// dinv/selfw + CSR slot allocation via warp-aggregated atomic (no global scan needed;
// slot ordering is irrelevant for a commutative-enough fp32 sum at 1e-3 tolerance).
__global__ void dinv_alloc_kernel() {
    int i = blockIdx.x * 256 + threadIdx.x;   // NN % 256 == 0, all threads valid
    int lane = threadIdx.x & 31;
    int d = g_deg[i];
    float dd = (float)(d + 1);                // +1 self loop
    g_dinv[i]  = rsqrtf(dd);
    g_selfw[i] = 1.0f / dd;
    int incl = d;
    #pragma unroll
    for (int off = 1; off < 32; off <<= 1) {
        int v = __shfl_up_sync(0xffffffffu, incl, off);
        if (lane >= off) incl += v;
    }
    int tot = __shfl_sync(0xffffffffu, incl, 31);
    int base = 0;
    if (lane == 31) base = atomicAdd(&g_counter, tot);
    base = __shfl_sync(0xffffffffu, base, 31);
    g_start[i] = base + incl - d;
}

__global__ void fill_kernel(const int* __restrict__ ei) {
    int t = blockIdx.x * 256 + threadIdx.x;
    if (t >= ET) return;
    int b = t / EP, j = t - b * EP;
    const int* bp = ei + b * 2 * EP;
    int s = bp[j];
    int dte = bp[EP + j];
    int pos = g_start[dte] + atomicAdd(&g_fill[dte], 1);
    float nrm = g_dinv[s] * g_dinv[dte];
    g_entries[pos] = make_int2(s, __float_as_int(nrm));
}

// ---------------- aggregation: out[i] = selfw[i]*in[i] + sum_e norm*in[src] ----------------
// C lanes per node (channel per lane). Optional epilogue: relu(acc + bias).
template<int C, bool EPI>
__global__ void agg_kernel(const float* __restrict__ in, float* __restrict__ out,
                           const float* __restrict__ bias) {
    constexpr int GROUPS = 256 / C;
    int g = threadIdx.x / C;
    int c = threadIdx.x - g * C;
    int node = blockIdx.x * GROUPS + g;
    if (node >= NN) return;

    int start = g_start[node];
    int deg   = g_deg[node];
    float acc = g_selfw[node] * in[node * C + c];

    int k = start, end = start + deg;
    if (k < end) {
        int2 e = g_entries[k];
        while (++k < end) {
            int2 en = g_entries[k];                       // prefetch next entry
            acc += __int_as_float(e.y) * __ldg(&in[e.x * C + c]);
            e = en;
        }
        acc += __int_as_float(e.y) * __ldg(&in[e.x * C + c]);
    }
    if (EPI) acc = fmaxf(acc + bias[c], 0.0f);
    out[node * C + c] = acc;
}

// ---------------- small GEMM: out[N,COUT] = (in[N,CIN] @ W) (+bias, relu) ----------------
template<int CIN, int COUT, bool BIASRELU>
__global__ __launch_bounds__(128) void gemm_kernel(const float* __restrict__ in,
                                                   const float* __restrict__ W,
                                                   const float* __restrict__ bias,
                                                   float* __restrict__ out) {
    constexpr int ROWS = 128;
    __shared__ float sW[CIN * COUT];
    __shared__ float sBuf[ROWS * 65];   // padded staging, reused in/out
    int t = threadIdx.x;
    int rowBase = blockIdx.x * ROWS;    // NN % 128 == 0

    for (int i = t; i < CIN * COUT; i += 128) sW[i] = W[i];
    for (int i = t; i < ROWS * CIN; i += 128) {
        int r = i / CIN, col = i - r * CIN;
        sBuf[r * (CIN + 1) + col] = in[rowBase * CIN + i];   // coalesced global read
    }
    __syncthreads();

    float acc[COUT];
    #pragma unroll
    for (int c = 0; c < COUT; c++) acc[c] = 0.0f;
    #pragma unroll
    for (int i = 0; i < CIN; i++) {
        float xi = sBuf[t * (CIN + 1) + i];
        #pragma unroll
        for (int c = 0; c < COUT; c++) acc[c] += xi * sW[i * COUT + c];
    }
    __syncthreads();
    #pragma unroll
    for (int c = 0; c < COUT; c++) {
        float v = acc[c];
        if (BIASRELU) v = fmaxf(v + bias[c], 0.0f);
        sBuf[t * (COUT + 1) + c] = v;
    }
    __syncthreads();
    for (int i = t; i < ROWS * COUT; i += 128) {
        int r = i / COUT, col = i - r * COUT;
        out[rowBase * COUT + i] = sBuf[r * (COUT + 1) + col];   // coalesced global write
    }
}

// ---------------- final MLP: out = relu(h@fW1+fb1)@fW2+fb2  (16 -> 16 -> 9) ----------------
__global__ __launch_bounds__(128) void mlp_kernel(const float* __restrict__ h,
                                                  const float* __restrict__ fW1,
                                                  const float* __restrict__ fb1,
                                                  const float* __restrict__ fW2,
                                                  const float* __restrict__ fb2,
                                                  float* __restrict__ out) {
    constexpr int ROWS = 128;
    __shared__ float sW1[16 * 16];
    __shared__ float sW2[16 * 9];
    __shared__ float sB1[16];
    __shared__ float sB2[9];
    __shared__ float sBuf[ROWS * 17];
    int t = threadIdx.x;
    int rowBase = blockIdx.x * ROWS;

    if (t < 256) { }  // no-op
    for (int i = t; i < 256; i += 128) sW1[i] = fW1[i];
    for (int i = t; i < 144; i += 128) sW2[i] = fW2[i];
    if (t < 16) sB1[t] = fb1[t];
    if (t < 9)  sB2[t] = fb2[t];
    for (int i = t; i < ROWS * 16; i += 128) {
        int r = i / 16, col = i - r * 16;
        sBuf[r * 17 + col] = h[rowBase * 16 + i];
    }
    __syncthreads();

    float x[16];
    #pragma unroll
    for (int i = 0; i < 16; i++) x[i] = sBuf[t * 17 + i];
    float m[16];
    #pragma unroll
    for (int o = 0; o < 16; o++) {
        float a = sB1[o];
        #pragma unroll
        for (int i = 0; i < 16; i++) a += x[i] * sW1[i * 16 + o];
        m[o] = fmaxf(a, 0.0f);
    }
    float y[9];
    #pragma unroll
    for (int c = 0; c < 9; c++) {
        float a = sB2[c];
        #pragma unroll
        for (int o = 0; o < 16; o++) a += m[o] * sW2[o * 9 + c];
        y[c] = a;
    }
    __syncthreads();
    #pragma unroll
    for (int c = 0; c < 9; c++) sBuf[t * 10 + c] = y[c];
    __syncthreads();
    for (int i = t; i < ROWS * 9; i += 128) {
        int r = i / 9, col = i - r * 9;
        out[rowBase * 9 + i] = sBuf[r * 10 + col];
    }
}

// ---------------- launch ----------------
extern "C" void kernel_launch(void* const* d_in, const int* in_sizes, int n_in,
                              void* d_out, int out_size) {
    const float* x   = (const float*)d_in[0];
    const int*   ei  = (const int*)d_in[1];
    const float* W1  = (const float*)d_in[2];
    const float* b1  = (const float*)d_in[3];
    const float* W2  = (const float*)d_in[4];
    const float* b2  = (const float*)d_in[5];
    const float* W3  = (const float*)d_in[6];
    const float* b3  = (const float*)d_in[7];
    const float* W4  = (const float*)d_in[8];
    const float* b4  = (const float*)d_in[9];
    const float* W5  = (const float*)d_in[10];
    const float* b5  = (const float*)d_in[11];
    const float* fW1 = (const float*)d_in[12];
    const float* fb1 = (const float*)d_in[13];
    const float* fW2 = (const float*)d_in[14];
    const float* fb2 = (const float*)d_in[15];
    float* out = (float*)d_out;

    float* A; float* B;
    cudaGetSymbolAddress((void**)&A, g_bufA);
    cudaGetSymbolAddress((void**)&B, g_bufB);

    const int nb_nodes = NN / 256;        // 648
    const int nb_edges = ET / 256;        // 12960
    const int nb_rows  = NN / 128;        // 1296

    // graph build
    zero_kernel<<<nb_nodes + 1, 256>>>();
    count_kernel<<<nb_edges, 256>>>(ei);
    dinv_alloc_kernel<<<nb_nodes, 256>>>();
    fill_kernel<<<nb_edges, 256>>>(ei);

    // L1 (10->16): GEMM first, aggregate 16ch with epilogue (+b1, relu)
    gemm_kernel<10, 16, false><<<nb_rows, 128>>>(x, W1, nullptr, A);
    agg_kernel<16, true><<<NN / 16, 256>>>(A, B, b1);
    // L2 (16->32): aggregate first (16ch), GEMM with bias+relu
    agg_kernel<16, false><<<NN / 16, 256>>>(B, A, nullptr);
    gemm_kernel<16, 32, true><<<nb_rows, 128>>>(A, W2, b2, B);
    // L3 (32->64): aggregate first (32ch), GEMM with bias+relu
    agg_kernel<32, false><<<NN / 8, 256>>>(B, A, nullptr);
    gemm_kernel<32, 64, true><<<nb_rows, 128>>>(A, W3, b3, B);
    // L4 (64->32): GEMM first (32ch agg), epilogue (+b4, relu)
    gemm_kernel<64, 32, false><<<nb_rows, 128>>>(B, W4, nullptr, A);
    agg_kernel<32, true><<<NN / 8, 256>>>(A, B, b4);
    // L5 (32->16): GEMM first (16ch agg), epilogue (+b5, relu)
    gemm_kernel<32, 16, false><<<nb_rows, 128>>>(B, W5, nullptr, A);
    agg_kernel<16, true><<<NN / 16, 256>>>(A, B, b5);
    // final MLP 16->16->9
    mlp_kernel<<<nb_rows, 128>>>(B, fW1, fb1, fW2, fb2, out);
}

// round 2
// speedup vs baseline: 1.0086x; 1.0086x over previous
#include <cuda_runtime.h>
#include <cuda_bf16.h>

// ---------------- problem constants ----------------
#define NN 165888            // B*81 nodes
#define BB 2048
#define EP 1620
#define ET (BB*EP)           // 3,317,760 edges (plus NN implicit self loops)

// ---------------- device scratch (no allocation allowed) ----------------
__device__ int   g_deg[NN];
__device__ int   g_fill[NN];
__device__ int   g_start[NN];
__device__ float g_dinv[NN];
__device__ float g_selfw[NN];
__device__ int2  g_entries[ET];      // (src, norm-as-bits)
__device__ float g_bufA[NN * 64];
__device__ float g_bufB[NN * 64];
__device__ int   g_counter;

// ---------------- graph build ----------------
__global__ void zero_kernel() {
    int i = blockIdx.x * 256 + threadIdx.x;
    if (i < NN) { g_deg[i] = 0; g_fill[i] = 0; }
    if (i == 0) g_counter = 0;
}

__global__ void count_kernel(const int* __restrict__ ei) {
    int t = blockIdx.x * 256 + threadIdx.x;
    if (t >= ET) return;
    int b = t / EP, j = t - b * EP;
    int dst = ei[(b * 2 + 1) * EP + j];
    atomicAdd(&g_deg[dst], 1);
}

// dinv/selfw + CSR slot allocation via warp-aggregated atomic (no global scan needed;
// slot ordering is irrelevant for a commutative-enough fp32 sum at 1e-3 tolerance).
__global__ void dinv_alloc_kernel() {
    int i = blockIdx.x * 256 + threadIdx.x;   // NN % 256 == 0, all threads valid
    int lane = threadIdx.x & 31;
    int d = g_deg[i];
    float dd = (float)(d + 1);                // +1 self loop
    g_dinv[i]  = rsqrtf(dd);
    g_selfw[i] = 1.0f / dd;
    int incl = d;
    #pragma unroll
    for (int off = 1; off < 32; off <<= 1) {
        int v = __shfl_up_sync(0xffffffffu, incl, off);
        if (lane >= off) incl += v;
    }
    int tot = __shfl_sync(0xffffffffu, incl, 31);
    int base = 0;
    if (lane == 31) base = atomicAdd(&g_counter, tot);
    base = __shfl_sync(0xffffffffu, base, 31);
    g_start[i] = base + incl - d;
}

__global__ void fill_kernel(const int* __restrict__ ei) {
    int t = blockIdx.x * 256 + threadIdx.x;
    if (t >= ET) return;
    int b = t / EP, j = t - b * EP;
    const int* bp = ei + b * 2 * EP;
    int s = bp[j];
    int dte = bp[EP + j];
    int pos = g_start[dte] + atomicAdd(&g_fill[dte], 1);
    float nrm = g_dinv[s] * g_dinv[dte];
    g_entries[pos] = make_int2(s, __float_as_int(nrm));
}

// ---------------- aggregation: out[i] = selfw[i]*in[i] + sum_e norm*in[src] ----------------
// C lanes per node (channel per lane). Optional epilogue: relu(acc + bias).
template<int C, bool EPI>
__global__ void agg_kernel(const float* __restrict__ in, float* __restrict__ out,
                           const float* __restrict__ bias) {
    constexpr int GROUPS = 256 / C;
    int g = threadIdx.x / C;
    int c = threadIdx.x - g * C;
    int node = blockIdx.x * GROUPS + g;
    if (node >= NN) return;

    int start = g_start[node];
    int deg   = g_deg[node];
    float acc = g_selfw[node] * in[node * C + c];

    int k = start, end = start + deg;
    if (k < end) {
        int2 e = g_entries[k];
        while (++k < end) {
            int2 en = g_entries[k];                       // prefetch next entry
            acc += __int_as_float(e.y) * __ldg(&in[e.x * C + c]);
            e = en;
        }
        acc += __int_as_float(e.y) * __ldg(&in[e.x * C + c]);
    }
    if (EPI) acc = fmaxf(acc + bias[c], 0.0f);
    out[node * C + c] = acc;
}

// ---------------- small GEMM: out[N,COUT] = (in[N,CIN] @ W) (+bias, relu) ----------------
template<int CIN, int COUT, bool BIASRELU>
__global__ __launch_bounds__(128) void gemm_kernel(const float* __restrict__ in,
                                                   const float* __restrict__ W,
                                                   const float* __restrict__ bias,
                                                   float* __restrict__ out) {
    constexpr int ROWS = 128;
    __shared__ float sW[CIN * COUT];
    __shared__ float sBuf[ROWS * 65];   // padded staging, reused in/out
    int t = threadIdx.x;
    int rowBase = blockIdx.x * ROWS;    // NN % 128 == 0

    for (int i = t; i < CIN * COUT; i += 128) sW[i] = W[i];
    for (int i = t; i < ROWS * CIN; i += 128) {
        int r = i / CIN, col = i - r * CIN;
        sBuf[r * (CIN + 1) + col] = in[rowBase * CIN + i];   // coalesced global read
    }
    __syncthreads();

    float acc[COUT];
    #pragma unroll
    for (int c = 0; c < COUT; c++) acc[c] = 0.0f;
    #pragma unroll
    for (int i = 0; i < CIN; i++) {
        float xi = sBuf[t * (CIN + 1) + i];
        #pragma unroll
        for (int c = 0; c < COUT; c++) acc[c] += xi * sW[i * COUT + c];
    }
    __syncthreads();
    #pragma unroll
    for (int c = 0; c < COUT; c++) {
        float v = acc[c];
        if (BIASRELU) v = fmaxf(v + bias[c], 0.0f);
        sBuf[t * (COUT + 1) + c] = v;
    }
    __syncthreads();
    for (int i = t; i < ROWS * COUT; i += 128) {
        int r = i / COUT, col = i - r * COUT;
        out[rowBase * COUT + i] = sBuf[r * (COUT + 1) + col];   // coalesced global write
    }
}

// ---------------- final MLP: out = relu(h@fW1+fb1)@fW2+fb2  (16 -> 16 -> 9) ----------------
__global__ __launch_bounds__(128) void mlp_kernel(const float* __restrict__ h,
                                                  const float* __restrict__ fW1,
                                                  const float* __restrict__ fb1,
                                                  const float* __restrict__ fW2,
                                                  const float* __restrict__ fb2,
                                                  float* __restrict__ out) {
    constexpr int ROWS = 128;
    __shared__ float sW1[16 * 16];
    __shared__ float sW2[16 * 9];
    __shared__ float sB1[16];
    __shared__ float sB2[9];
    __shared__ float sBuf[ROWS * 17];
    int t = threadIdx.x;
    int rowBase = blockIdx.x * ROWS;

    if (t < 256) { }  // no-op
    for (int i = t; i < 256; i += 128) sW1[i] = fW1[i];
    for (int i = t; i < 144; i += 128) sW2[i] = fW2[i];
    if (t < 16) sB1[t] = fb1[t];
    if (t < 9)  sB2[t] = fb2[t];
    for (int i = t; i < ROWS * 16; i += 128) {
        int r = i / 16, col = i - r * 16;
        sBuf[r * 17 + col] = h[rowBase * 16 + i];
    }
    __syncthreads();

    float x[16];
    #pragma unroll
    for (int i = 0; i < 16; i++) x[i] = sBuf[t * 17 + i];
    float m[16];
    #pragma unroll
    for (int o = 0; o < 16; o++) {
        float a = sB1[o];
        #pragma unroll
        for (int i = 0; i < 16; i++) a += x[i] * sW1[i * 16 + o];
        m[o] = fmaxf(a, 0.0f);
    }
    float y[9];
    #pragma unroll
    for (int c = 0; c < 9; c++) {
        float a = sB2[c];
        #pragma unroll
        for (int o = 0; o < 16; o++) a += m[o] * sW2[o * 9 + c];
        y[c] = a;
    }
    __syncthreads();
    #pragma unroll
    for (int c = 0; c < 9; c++) sBuf[t * 10 + c] = y[c];
    __syncthreads();
    for (int i = t; i < ROWS * 9; i += 128) {
        int r = i / 9, col = i - r * 9;
        out[rowBase * 9 + i] = sBuf[r * 10 + col];
    }
}

// ---------------- launch ----------------
extern "C" void kernel_launch(void* const* d_in, const int* in_sizes, int n_in,
                              void* d_out, int out_size) {
    const float* x   = (const float*)d_in[0];
    const int*   ei  = (const int*)d_in[1];
    const float* W1  = (const float*)d_in[2];
    const float* b1  = (const float*)d_in[3];
    const float* W2  = (const float*)d_in[4];
    const float* b2  = (const float*)d_in[5];
    const float* W3  = (const float*)d_in[6];
    const float* b3  = (const float*)d_in[7];
    const float* W4  = (const float*)d_in[8];
    const float* b4  = (const float*)d_in[9];
    const float* W5  = (const float*)d_in[10];
    const float* b5  = (const float*)d_in[11];
    const float* fW1 = (const float*)d_in[12];
    const float* fb1 = (const float*)d_in[13];
    const float* fW2 = (const float*)d_in[14];
    const float* fb2 = (const float*)d_in[15];
    float* out = (float*)d_out;

    float* A; float* B;
    cudaGetSymbolAddress((void**)&A, g_bufA);
    cudaGetSymbolAddress((void**)&B, g_bufB);

    const int nb_nodes = NN / 256;        // 648
    const int nb_edges = ET / 256;        // 12960
    const int nb_rows  = NN / 128;        // 1296

    // graph build
    zero_kernel<<<nb_nodes + 1, 256>>>();
    count_kernel<<<nb_edges, 256>>>(ei);
    dinv_alloc_kernel<<<nb_nodes, 256>>>();
    fill_kernel<<<nb_edges, 256>>>(ei);

    // L1 (10->16): GEMM first, aggregate 16ch with epilogue (+b1, relu)
    gemm_kernel<10, 16, false><<<nb_rows, 128>>>(x, W1, nullptr, A);
    agg_kernel<16, true><<<NN / 16, 256>>>(A, B, b1);
    // L2 (16->32): aggregate first (16ch), GEMM with bias+relu
    agg_kernel<16, false><<<NN / 16, 256>>>(B, A, nullptr);
    gemm_kernel<16, 32, true><<<nb_rows, 128>>>(A, W2, b2, B);
    // L3 (32->64): aggregate first (32ch), GEMM with bias+relu
    agg_kernel<32, false><<<NN / 8, 256>>>(B, A, nullptr);
    gemm_kernel<32, 64, true><<<nb_rows, 128>>>(A, W3, b3, B);
    // L4 (64->32): GEMM first (32ch agg), epilogue (+b4, relu)
    gemm_kernel<64, 32, false><<<nb_rows, 128>>>(B, W4, nullptr, A);
    agg_kernel<32, true><<<NN / 8, 256>>>(A, B, b4);
    // L5 (32->16): GEMM first (16ch agg), epilogue (+b5, relu)
    gemm_kernel<32, 16, false><<<nb_rows, 128>>>(B, W5, nullptr, A);
    agg_kernel<16, true><<<NN / 16, 256>>>(A, B, b5);
    // final MLP 16->16->9
    mlp_kernel<<<nb_rows, 128>>>(B, fW1, fb1, fW2, fb2, out);
}

// round 3
// speedup vs baseline: 1.0122x; 1.0035x over previous
#include <cuda_runtime.h>
#include <cuda_bf16.h>

// ---------------- problem constants ----------------
#define NN 165888            // B*81 nodes
#define BB 2048
#define EP 1620
#define ET (BB*EP)           // 3,317,760 edges (plus NN implicit self loops)

// ---------------- device scratch (no allocation allowed) ----------------
__device__ int   g_deg[NN];
__device__ int   g_fill[NN];
__device__ int   g_start[NN];
__device__ float g_dinv[NN];
__device__ float g_selfw[NN];
__device__ int2  g_entries[ET];      // (src, norm-as-bits)
__device__ float g_bufA[NN * 64];
__device__ float g_bufB[NN * 64];
__device__ int   g_counter;

// ---------------- graph build ----------------
__global__ void zero_kernel() {
    int i = blockIdx.x * 256 + threadIdx.x;
    if (i < NN) { g_deg[i] = 0; g_fill[i] = 0; }
    if (i == 0) g_counter = 0;
}

__global__ void count_kernel(const int* __restrict__ ei) {
    int t = blockIdx.x * 256 + threadIdx.x;
    if (t >= ET) return;
    int b = t / EP, j = t - b * EP;
    int dst = ei[(b * 2 + 1) * EP + j];
    atomicAdd(&g_deg[dst], 1);
}

// dinv/selfw + CSR slot allocation via warp-aggregated atomic (no global scan needed;
// slot ordering is irrelevant for a commutative-enough fp32 sum at 1e-3 tolerance).
__global__ void dinv_alloc_kernel() {
    int i = blockIdx.x * 256 + threadIdx.x;   // NN % 256 == 0, all threads valid
    int lane = threadIdx.x & 31;
    int d = g_deg[i];
    float dd = (float)(d + 1);                // +1 self loop
    g_dinv[i]  = rsqrtf(dd);
    g_selfw[i] = 1.0f / dd;
    int incl = d;
    #pragma unroll
    for (int off = 1; off < 32; off <<= 1) {
        int v = __shfl_up_sync(0xffffffffu, incl, off);
        if (lane >= off) incl += v;
    }
    int tot = __shfl_sync(0xffffffffu, incl, 31);
    int base = 0;
    if (lane == 31) base = atomicAdd(&g_counter, tot);
    base = __shfl_sync(0xffffffffu, base, 31);
    g_start[i] = base + incl - d;
}

__global__ void fill_kernel(const int* __restrict__ ei) {
    int t = blockIdx.x * 256 + threadIdx.x;
    if (t >= ET) return;
    int b = t / EP, j = t - b * EP;
    const int* bp = ei + b * 2 * EP;
    int s = bp[j];
    int dte = bp[EP + j];
    int pos = g_start[dte] + atomicAdd(&g_fill[dte], 1);
    float nrm = g_dinv[s] * g_dinv[dte];
    g_entries[pos] = make_int2(s, __float_as_int(nrm));
}

// ---------------- aggregation: out[i] = selfw[i]*in[i] + sum_e norm*in[src] ----------------
// C lanes per node (channel per lane). Optional epilogue: relu(acc + bias).
template<int C, bool EPI>
__global__ void agg_kernel(const float* __restrict__ in, float* __restrict__ out,
                           const float* __restrict__ bias) {
    constexpr int GROUPS = 256 / C;
    int g = threadIdx.x / C;
    int c = threadIdx.x - g * C;
    int node = blockIdx.x * GROUPS + g;
    if (node >= NN) return;

    int start = g_start[node];
    int deg   = g_deg[node];
    float acc = g_selfw[node] * in[node * C + c];

    int k = start, end = start + deg;
    if (k < end) {
        int2 e = g_entries[k];
        while (++k < end) {
            int2 en = g_entries[k];                       // prefetch next entry
            acc += __int_as_float(e.y) * __ldg(&in[e.x * C + c]);
            e = en;
        }
        acc += __int_as_float(e.y) * __ldg(&in[e.x * C + c]);
    }
    if (EPI) acc = fmaxf(acc + bias[c], 0.0f);
    out[node * C + c] = acc;
}

// ---------------- small GEMM: out[N,COUT] = (in[N,CIN] @ W) (+bias, relu) ----------------
template<int CIN, int COUT, bool BIASRELU>
__global__ __launch_bounds__(128) void gemm_kernel(const float* __restrict__ in,
                                                   const float* __restrict__ W,
                                                   const float* __restrict__ bias,
                                                   float* __restrict__ out) {
    constexpr int ROWS = 128;
    __shared__ float sW[CIN * COUT];
    __shared__ float sBuf[ROWS * 65];   // padded staging, reused in/out
    int t = threadIdx.x;
    int rowBase = blockIdx.x * ROWS;    // NN % 128 == 0

    for (int i = t; i < CIN * COUT; i += 128) sW[i] = W[i];
    for (int i = t; i < ROWS * CIN; i += 128) {
        int r = i / CIN, col = i - r * CIN;
        sBuf[r * (CIN + 1) + col] = in[rowBase * CIN + i];   // coalesced global read
    }
    __syncthreads();

    float acc[COUT];
    #pragma unroll
    for (int c = 0; c < COUT; c++) acc[c] = 0.0f;
    #pragma unroll
    for (int i = 0; i < CIN; i++) {
        float xi = sBuf[t * (CIN + 1) + i];
        #pragma unroll
        for (int c = 0; c < COUT; c++) acc[c] += xi * sW[i * COUT + c];
    }
    __syncthreads();
    #pragma unroll
    for (int c = 0; c < COUT; c++) {
        float v = acc[c];
        if (BIASRELU) v = fmaxf(v + bias[c], 0.0f);
        sBuf[t * (COUT + 1) + c] = v;
    }
    __syncthreads();
    for (int i = t; i < ROWS * COUT; i += 128) {
        int r = i / COUT, col = i - r * COUT;
        out[rowBase * COUT + i] = sBuf[r * (COUT + 1) + col];   // coalesced global write
    }
}

// ---------------- final MLP: out = relu(h@fW1+fb1)@fW2+fb2  (16 -> 16 -> 9) ----------------
__global__ __launch_bounds__(128) void mlp_kernel(const float* __restrict__ h,
                                                  const float* __restrict__ fW1,
                                                  const float* __restrict__ fb1,
                                                  const float* __restrict__ fW2,
                                                  const float* __restrict__ fb2,
                                                  float* __restrict__ out) {
    constexpr int ROWS = 128;
    __shared__ float sW1[16 * 16];
    __shared__ float sW2[16 * 9];
    __shared__ float sB1[16];
    __shared__ float sB2[9];
    __shared__ float sBuf[ROWS * 17];
    int t = threadIdx.x;
    int rowBase = blockIdx.x * ROWS;

    if (t < 256) { }  // no-op
    for (int i = t; i < 256; i += 128) sW1[i] = fW1[i];
    for (int i = t; i < 144; i += 128) sW2[i] = fW2[i];
    if (t < 16) sB1[t] = fb1[t];
    if (t < 9)  sB2[t] = fb2[t];
    for (int i = t; i < ROWS * 16; i += 128) {
        int r = i / 16, col = i - r * 16;
        sBuf[r * 17 + col] = h[rowBase * 16 + i];
    }
    __syncthreads();

    float x[16];
    #pragma unroll
    for (int i = 0; i < 16; i++) x[i] = sBuf[t * 17 + i];
    float m[16];
    #pragma unroll
    for (int o = 0; o < 16; o++) {
        float a = sB1[o];
        #pragma unroll
        for (int i = 0; i < 16; i++) a += x[i] * sW1[i * 16 + o];
        m[o] = fmaxf(a, 0.0f);
    }
    float y[9];
    #pragma unroll
    for (int c = 0; c < 9; c++) {
        float a = sB2[c];
        #pragma unroll
        for (int o = 0; o < 16; o++) a += m[o] * sW2[o * 9 + c];
        y[c] = a;
    }
    __syncthreads();
    #pragma unroll
    for (int c = 0; c < 9; c++) sBuf[t * 10 + c] = y[c];
    __syncthreads();
    for (int i = t; i < ROWS * 9; i += 128) {
        int r = i / 9, col = i - r * 9;
        out[rowBase * 9 + i] = sBuf[r * 10 + col];
    }
}

// ---------------- launch ----------------
extern "C" void kernel_launch(void* const* d_in, const int* in_sizes, int n_in,
                              void* d_out, int out_size) {
    const float* x   = (const float*)d_in[0];
    const int*   ei  = (const int*)d_in[1];
    const float* W1  = (const float*)d_in[2];
    const float* b1  = (const float*)d_in[3];
    const float* W2  = (const float*)d_in[4];
    const float* b2  = (const float*)d_in[5];
    const float* W3  = (const float*)d_in[6];
    const float* b3  = (const float*)d_in[7];
    const float* W4  = (const float*)d_in[8];
    const float* b4  = (const float*)d_in[9];
    const float* W5  = (const float*)d_in[10];
    const float* b5  = (const float*)d_in[11];
    const float* fW1 = (const float*)d_in[12];
    const float* fb1 = (const float*)d_in[13];
    const float* fW2 = (const float*)d_in[14];
    const float* fb2 = (const float*)d_in[15];
    float* out = (float*)d_out;

    float* A; float* B;
    cudaGetSymbolAddress((void**)&A, g_bufA);
    cudaGetSymbolAddress((void**)&B, g_bufB);

    const int nb_nodes = NN / 256;        // 648
    const int nb_edges = ET / 256;        // 12960
    const int nb_rows  = NN / 128;        // 1296

    // graph build
    zero_kernel<<<nb_nodes + 1, 256>>>();
    count_kernel<<<nb_edges, 256>>>(ei);
    dinv_alloc_kernel<<<nb_nodes, 256>>>();
    fill_kernel<<<nb_edges, 256>>>(ei);

    // L1 (10->16): GEMM first, aggregate 16ch with epilogue (+b1, relu)
    gemm_kernel<10, 16, false><<<nb_rows, 128>>>(x, W1, nullptr, A);
    agg_kernel<16, true><<<NN / 16, 256>>>(A, B, b1);
    // L2 (16->32): aggregate first (16ch), GEMM with bias+relu
    agg_kernel<16, false><<<NN / 16, 256>>>(B, A, nullptr);
    gemm_kernel<16, 32, true><<<nb_rows, 128>>>(A, W2, b2, B);
    // L3 (32->64): aggregate first (32ch), GEMM with bias+relu
    agg_kernel<32, false><<<NN / 8, 256>>>(B, A, nullptr);
    gemm_kernel<32, 64, true><<<nb_rows, 128>>>(A, W3, b3, B);
    // L4 (64->32): GEMM first (32ch agg), epilogue (+b4, relu)
    gemm_kernel<64, 32, false><<<nb_rows, 128>>>(B, W4, nullptr, A);
    agg_kernel<32, true><<<NN / 8, 256>>>(A, B, b4);
    // L5 (32->16): GEMM first (16ch agg), epilogue (+b5, relu)
    gemm_kernel<32, 16, false><<<nb_rows, 128>>>(B, W5, nullptr, A);
    agg_kernel<16, true><<<NN / 16, 256>>>(A, B, b5);
    // final MLP 16->16->9
    mlp_kernel<<<nb_rows, 128>>>(B, fW1, fb1, fW2, fb2, out);
}